// round 2
// baseline (speedup 1.0000x reference)
#include <cuda_runtime.h>

// ---------------------------------------------------------------------------
// 2-layer GCN collapsed to scalar graph ops (feature dims are 1 -> H -> 1,
// and aggregation is linear, so each layer reduces to a scalar scatter-add).
//   deg[v]   = #in-edges + 1 (self loop)
//   dis[v]   = rsqrt(deg[v])
//   s1[v]    = dis[v] * ( sum_{u->v} dis[u]*x[u]  +  dis[v]*x[v] )
//   t[v]     = sum_k relu(s1[v]*W1[k] + b1[k]) * W2[k]
//   out[v]   = dis[v] * ( sum_{u->v} dis[u]*t[u]  +  dis[v]*t[v] ) + b2
// edge_index is int32 on the wire (JAX x64 disabled downcasts int64->int32).
// ---------------------------------------------------------------------------

#define MAXN 100352   // >= N_NODES (100000), padded

__device__ float g_deg[MAXN];
__device__ float g_dis[MAXN];
__device__ float g_val[MAXN];   // pre-scaled message value (dis[u]*feat[u])
__device__ float g_acc[MAXN];   // scatter accumulator

__global__ void k_zero_deg(int n) {
    int v = blockIdx.x * blockDim.x + threadIdx.x;
    if (v < n) g_deg[v] = 0.0f;
}

// degree count, 4 edges / thread via 128-bit loads; scalar tail in-kernel
__global__ void k_deg_vec4(const int* __restrict__ dst, int E) {
    int i = (blockIdx.x * blockDim.x + threadIdx.x) * 4;
    if (i + 3 < E) {
        int4 d = *reinterpret_cast<const int4*>(dst + i);
        atomicAdd(&g_deg[d.x], 1.0f);
        atomicAdd(&g_deg[d.y], 1.0f);
        atomicAdd(&g_deg[d.z], 1.0f);
        atomicAdd(&g_deg[d.w], 1.0f);
    } else {
        for (; i < E; ++i) atomicAdd(&g_deg[dst[i]], 1.0f);
    }
}

__global__ void k_deg_scalar(const int* __restrict__ dst, int E) {
    int i = blockIdx.x * blockDim.x + threadIdx.x;
    if (i < E) atomicAdd(&g_deg[dst[i]], 1.0f);
}

__global__ void k_nodeA(const float* __restrict__ x, int n) {
    int v = blockIdx.x * blockDim.x + threadIdx.x;
    if (v < n) {
        float d = rsqrtf(g_deg[v] + 1.0f);   // +1 self-loop; always >= 1
        g_dis[v] = d;
        g_val[v] = d * x[v];
        g_acc[v] = 0.0f;
    }
}

// scatter: acc[dst] += val[src], 4 edges / thread via 128-bit index loads
__global__ void k_edge_vec4(const int* __restrict__ src,
                            const int* __restrict__ dst, int E) {
    int i = (blockIdx.x * blockDim.x + threadIdx.x) * 4;
    if (i + 3 < E) {
        int4 s = *reinterpret_cast<const int4*>(src + i);
        int4 d = *reinterpret_cast<const int4*>(dst + i);
        float v0 = __ldg(&g_val[s.x]);
        float v1 = __ldg(&g_val[s.y]);
        float v2 = __ldg(&g_val[s.z]);
        float v3 = __ldg(&g_val[s.w]);
        atomicAdd(&g_acc[d.x], v0);
        atomicAdd(&g_acc[d.y], v1);
        atomicAdd(&g_acc[d.z], v2);
        atomicAdd(&g_acc[d.w], v3);
    } else {
        for (; i < E; ++i)
            atomicAdd(&g_acc[dst[i]], __ldg(&g_val[src[i]]));
    }
}

__global__ void k_edge_scalar(const int* __restrict__ src,
                              const int* __restrict__ dst, int E) {
    int i = blockIdx.x * blockDim.x + threadIdx.x;
    if (i < E) atomicAdd(&g_acc[dst[i]], __ldg(&g_val[src[i]]));
}

// s1 -> MLP collapse -> next-layer pre-scaled message; also rezero acc
__global__ void k_nodeB(const float* __restrict__ W1,
                        const float* __restrict__ b1,
                        const float* __restrict__ W2,
                        int H, int n) {
    __shared__ float sw1[256], sb1[256], sw2[256];
    for (int k = threadIdx.x; k < H && k < 256; k += blockDim.x) {
        sw1[k] = W1[k];
        sb1[k] = b1[k];
        sw2[k] = W2[k];
    }
    __syncthreads();
    int v = blockIdx.x * blockDim.x + threadIdx.x;
    if (v < n) {
        float d = g_dis[v];
        float s = d * (g_acc[v] + g_val[v]);
        float t = 0.0f;
        #pragma unroll 8
        for (int k = 0; k < H; ++k)
            t += fmaxf(fmaf(s, sw1[k], sb1[k]), 0.0f) * sw2[k];
        g_val[v] = d * t;
        g_acc[v] = 0.0f;
    }
}

__global__ void k_nodeC(float* __restrict__ out, const float* __restrict__ b2,
                        int n) {
    int v = blockIdx.x * blockDim.x + threadIdx.x;
    if (v < n) out[v] = g_dis[v] * (g_acc[v] + g_val[v]) + b2[0];
}

extern "C" void kernel_launch(void* const* d_in, const int* in_sizes, int n_in,
                              void* d_out, int out_size) {
    const float* x  = (const float*)d_in[0];
    const int*   ei = (const int*)d_in[1];     // int32 edge indices
    const float* W1 = (const float*)d_in[2];
    const float* b1 = (const float*)d_in[3];
    const float* W2 = (const float*)d_in[4];
    const float* b2 = (const float*)d_in[5];
    float*       out = (float*)d_out;

    int n = in_sizes[0];          // N nodes (x is [N,1])
    int E = in_sizes[1] / 2;      // edge_index is [2,E]
    int H = in_sizes[2];          // W1 is [1,H], H <= 256

    const int* src = ei;
    const int* dst = ei + E;

    const int TB = 256;
    int nb = (n + TB - 1) / TB;

    k_zero_deg<<<nb, TB>>>(n);

    // vec4 path needs the dst half 16B-aligned: E % 4 == 0 guarantees it
    bool vec_ok = ((E & 3) == 0);
    if (vec_ok) {
        int et = (E + 3) / 4;
        int eb = (et + TB - 1) / TB;
        k_deg_vec4<<<eb, TB>>>(dst, E);
        k_nodeA<<<nb, TB>>>(x, n);
        k_edge_vec4<<<eb, TB>>>(src, dst, E);
        k_nodeB<<<nb, TB>>>(W1, b1, W2, H, n);
        k_edge_vec4<<<eb, TB>>>(src, dst, E);
        k_nodeC<<<nb, TB>>>(out, b2, n);
    } else {
        int eb = (E + TB - 1) / TB;
        k_deg_scalar<<<eb, TB>>>(dst, E);
        k_nodeA<<<nb, TB>>>(x, n);
        k_edge_scalar<<<eb, TB>>>(src, dst, E);
        k_nodeB<<<nb, TB>>>(W1, b1, W2, H, n);
        k_edge_scalar<<<eb, TB>>>(src, dst, E);
        k_nodeC<<<nb, TB>>>(out, b2, n);
    }
}